// round 6
// baseline (speedup 1.0000x reference)
#include <cuda_runtime.h>

#define B   32
#define HH  512
#define NN  (512*512)          // 262144 per row
#define K1  180
#define K2  360
#define NTASK 96               // 3 arrays x 32 rows
#define THRESH_F 2.75f
#define CAP  4096
#define SCAP 2048
#define CH   16                // chunks per task
#define CHUNKF (NN/CH)         // 16384 floats per block

// Scratch (static device globals: allocation-free, zeroed at load)
__device__ int                 g_candCount[NTASK];
__device__ unsigned long long  g_cand[NTASK][CAP];
__device__ int                 g_topk[NTASK][K2];
__device__ float               g_loss[B];
__device__ int                 g_taskDone[NTASK];
__device__ int                 g_rowDone[B];
__device__ int                 g_done;

// Monotonic float -> uint (order-preserving), branchless
__device__ __forceinline__ unsigned orderKey(float f) {
    unsigned u = __float_as_uint(f);
    return u ^ (((unsigned)((int)u >> 31)) | 0x80000000u);
}

// Warp-aggregated emit of components >= THRESH_F
__device__ __forceinline__ void emit4(float4 v, unsigned gi0, int task) {
    float m = fmaxf(fmaxf(v.x, v.y), fmaxf(v.z, v.w));
    if (!__any_sync(0xffffffffu, m >= THRESH_F)) return;
    int lane = threadIdx.x & 31;
    float fx[4] = { v.x, v.y, v.z, v.w };
    #pragma unroll
    for (int c = 0; c < 4; c++) {
        bool pred = fx[c] >= THRESH_F;
        unsigned mask = __ballot_sync(0xffffffffu, pred);
        if (mask) {
            int leader = __ffs(mask) - 1;
            int base = 0;
            if (lane == leader)
                base = atomicAdd(&g_candCount[task], __popc(mask));
            base = __shfl_sync(0xffffffffu, base, leader);
            if (pred) {
                int pos = base + __popc(mask & ((1u << lane) - 1u));
                if (pos < CAP)
                    g_cand[task][pos] =
                        ((unsigned long long)orderKey(fx[c]) << 32) |
                        (unsigned)(~(gi0 + c));
            }
        }
    }
}

// ---------------------------------------------------------------------------
// ONE fused kernel: collect -> (last chunk) select -> (last select) coverage
//                   -> (last coverage) finalize + reset
// ---------------------------------------------------------------------------
__global__ void __launch_bounds__(512) fusedKernel(
        const float* __restrict__ rv,
        const float* __restrict__ ri,
        const float* __restrict__ rf,
        float* __restrict__ out) {
    __shared__ union SM {
        struct { unsigned long long sc[SCAP]; unsigned hist[1024]; } sel; // 20 KB
        unsigned bitmap[NN / 32];                                         // 32 KB
    } sm;
    __shared__ int s_n, s_flag, s_cover, s_denom;
    __shared__ unsigned s_binLo;
    __shared__ int s_rv[K1];

    int t = threadIdx.x;
    int task  = blockIdx.x >> 4;       // 0..95
    int chunk = blockIdx.x & 15;
    int a = task >> 5, row = task & 31;
    const float* src0 = (a == 0 ? rv : (a == 1 ? ri : rf)) + (size_t)row * NN;

    // ---------------- Phase 1: collect (streaming, MLP=8) ----------------
    {
        const float4* p = (const float4*)(src0 + (size_t)chunk * CHUNKF);
        unsigned idxBase = (unsigned)chunk * CHUNKF;
        float4 v[8];
        #pragma unroll
        for (int q = 0; q < 8; q++) v[q] = p[t + q * 512];   // batched loads
        #pragma unroll
        for (int q = 0; q < 8; q++)
            emit4(v[q], idxBase + (unsigned)(t + q * 512) * 4, task);
    }

    __threadfence();
    __syncthreads();
    if (t == 0)
        s_flag = (atomicAdd(&g_taskDone[task], 1) == CH - 1) ? 1 : 0;
    __syncthreads();
    if (!s_flag) return;

    // ---------------- Phase 2: exact top-k for this task ----------------
    {
        int need = (task < 2 * B) ? K1 : K2;
        int cnt = g_candCount[task];
        if (t == 0) s_n = 0;
        int n2;
        if (cnt >= need && cnt <= SCAP) {
            for (int i = t; i < cnt; i += 512) sm.sel.sc[i] = g_cand[task][i];
            __syncthreads();
            n2 = cnt;
        } else {
            // exact fallback: radix-hist rescan of this row (unreachable stats)
            for (int i = t; i < 1024; i += 512) sm.sel.hist[i] = 0;
            __syncthreads();
            for (int i = t; i < NN; i += 512)
                atomicAdd(&sm.sel.hist[orderKey(src0[i]) >> 22], 1u);
            __syncthreads();
            if (t == 0) {
                unsigned acc = 0; int bi = 0;
                for (int i = 1023; i >= 0; i--) {
                    acc += sm.sel.hist[i];
                    if (acc >= (unsigned)need) { bi = i; break; }
                }
                s_binLo = (unsigned)bi << 22;
            }
            __syncthreads();
            unsigned binLo = s_binLo;
            for (int i = t; i < NN; i += 512) {
                unsigned k = orderKey(src0[i]);
                if (k >= binLo) {
                    int pos = atomicAdd(&s_n, 1);
                    if (pos < SCAP)
                        sm.sel.sc[pos] = ((unsigned long long)k << 32) |
                                         (unsigned)(~(unsigned)i);
                }
            }
            __syncthreads();
            n2 = min(s_n, SCAP);
        }
        for (int i = t; i < n2; i += 512) {
            unsigned long long me = sm.sel.sc[i];
            int r = 0;
            #pragma unroll 4
            for (int j = 0; j < n2; j++) r += (sm.sel.sc[j] > me);
            if (r < need) g_topk[task][r] = (int)(~(unsigned)me);
        }
    }

    __threadfence();
    __syncthreads();
    if (t == 0)
        s_flag = (atomicAdd(&g_rowDone[row], 1) == 2) ? 1 : 0;
    __syncthreads();
    if (!s_flag) return;

    // ---------------- Phase 3: coverage for this row ----------------
    {
        int b = row;
        for (int i = t; i < NN / 32; i += 512) sm.bitmap[i] = 0;
        if (t == 0) { s_cover = 0; s_denom = 0; }
        for (int i = t; i < K1; i += 512) s_rv[i] = g_topk[0 * B + b][i];
        __syncthreads();

        // Dilate rf top-360 by Chebyshev radius 3
        if (t < K2) {
            int idx = g_topk[2 * B + b][t];
            int y = idx >> 9, x = idx & 511;
            int lo = max(x - 3, 0), hi = min(x + 3, 511);
            #pragma unroll
            for (int dy = -3; dy <= 3; dy++) {
                int yy = y + dy;
                if (yy < 0 || yy >= HH) continue;
                int wbase = yy << 4;
                int w0 = lo >> 5, w1 = hi >> 5;
                if (w0 == w1) {
                    unsigned m = ((1u << (hi - lo + 1)) - 1u) << (lo & 31);
                    atomicOr(&sm.bitmap[wbase + w0], m);
                } else {
                    atomicOr(&sm.bitmap[wbase + w0], 0xFFFFFFFFu << (lo & 31));
                    atomicOr(&sm.bitmap[wbase + w1], (1u << ((hi & 31) + 1)) - 1u);
                }
            }
        }
        __syncthreads();

        // Probe union of rv and (ri \ rv)
        if (t < K2) {
            int idx; bool isSrc;
            if (t < K1) { idx = s_rv[t]; isSrc = true; }
            else {
                idx = g_topk[1 * B + b][t - K1];
                isSrc = true;
                for (int j = 0; j < K1; j++)
                    if (s_rv[j] == idx) { isSrc = false; break; }
            }
            if (isSrc) {
                atomicAdd(&s_denom, 1);
                if ((sm.bitmap[idx >> 5] >> (idx & 31)) & 1u) atomicAdd(&s_cover, 1);
            }
        }
        __syncthreads();
        if (t == 0) {
            g_loss[b] = 1.0f - (float)s_cover / (float)max(s_denom, 1);
            __threadfence();
            s_flag = (atomicAdd(&g_done, 1) == B - 1) ? 1 : 0;
        }
        __syncthreads();
    }
    if (!s_flag) return;

    // ---------------- Phase 4: finalize + reset scratch ----------------
    if (t == 0) {
        __threadfence();
        volatile float* gl = g_loss;
        float s = 0.0f;
        for (int i = 0; i < B; i++) s += gl[i];
        out[0] = s / (float)B;
        g_done = 0;
    }
    if (t < NTASK) { g_candCount[t] = 0; g_taskDone[t] = 0; }
    if (t < B)     g_rowDone[t] = 0;
}

extern "C" void kernel_launch(void* const* d_in, const int* in_sizes, int n_in,
                              void* d_out, int out_size) {
    const float* rv = (const float*)d_in[0];
    const float* ri = (const float*)d_in[1];
    const float* rf = (const float*)d_in[2];
    fusedKernel<<<NTASK * CH, 512>>>(rv, ri, rf, (float*)d_out);
}

// round 7
// speedup vs baseline: 1.4659x; 1.4659x over previous
#include <cuda_runtime.h>

#define B   32
#define HH  512
#define NN  (512*512)          // 262144 per row
#define K1  180
#define K2  360
#define NTASK 96               // 3 arrays x 32 rows
#define THRESH_F 2.75f
#define KEYB16  0xC030u        // orderKey(2.75f) >> 16
#define CAP  4096
#define SCAP 2048
#define TCAP 512               // trimmed candidate cap
#define CH   32                // chunks per task
#define CHUNKF (NN/CH)         // 8192 floats per block

// Scratch (static device globals: allocation-free, zeroed at load)
__device__ int                 g_candCount[NTASK];
__device__ unsigned long long  g_cand[NTASK][CAP];
__device__ int                 g_topk[NTASK][K2];
__device__ float               g_loss[B];
__device__ int                 g_done;

// Monotonic float -> uint (order-preserving), branchless
__device__ __forceinline__ unsigned orderKey(float f) {
    unsigned u = __float_as_uint(f);
    return u ^ (((unsigned)((int)u >> 31)) | 0x80000000u);
}

// Warp-aggregated emit of components >= THRESH_F
__device__ __forceinline__ void emit4(float4 v, unsigned gi0, int task) {
    float m = fmaxf(fmaxf(v.x, v.y), fmaxf(v.z, v.w));
    if (!__any_sync(0xffffffffu, m >= THRESH_F)) return;
    int lane = threadIdx.x & 31;
    float fx[4] = { v.x, v.y, v.z, v.w };
    #pragma unroll
    for (int c = 0; c < 4; c++) {
        bool pred = fx[c] >= THRESH_F;
        unsigned mask = __ballot_sync(0xffffffffu, pred);
        if (mask) {
            int leader = __ffs(mask) - 1;
            int base = 0;
            if (lane == leader)
                base = atomicAdd(&g_candCount[task], __popc(mask));
            base = __shfl_sync(0xffffffffu, base, leader);
            if (pred) {
                int pos = base + __popc(mask & ((1u << lane) - 1u));
                if (pos < CAP)
                    g_cand[task][pos] =
                        ((unsigned long long)orderKey(fx[c]) << 32) |
                        (unsigned)(~(gi0 + c));
            }
        }
    }
}

// ---------------------------------------------------------------------------
// 1) Streaming collect: 256 thr/block, 8 batched float4 loads (MLP=8)
// ---------------------------------------------------------------------------
__global__ void __launch_bounds__(256) collectKernel(
        const float* __restrict__ rv,
        const float* __restrict__ ri,
        const float* __restrict__ rf) {
    int task  = blockIdx.x >> 5;       // 0..95
    int chunk = blockIdx.x & 31;
    int a = task >> 5, row = task & 31;

    const float* src = (a == 0 ? rv : (a == 1 ? ri : rf))
                       + (size_t)row * NN + (size_t)chunk * CHUNKF;
    const float4* p = (const float4*)src;
    unsigned idxBase = (unsigned)chunk * CHUNKF;
    int t = threadIdx.x;

    float4 v[8];
    #pragma unroll
    for (int q = 0; q < 8; q++) v[q] = p[t + q * 256];   // front-batched: MLP=8
    #pragma unroll
    for (int q = 0; q < 8; q++)
        emit4(v[q], idxBase + (unsigned)(t + q * 256) * 4, task);
}

// ---------------------------------------------------------------------------
// 2) Exact top-k per task: fine-hist trim (~780 -> ~400), then rank trimmed.
// ---------------------------------------------------------------------------
__global__ void __launch_bounds__(512) selectKernel(
        const float* __restrict__ rv,
        const float* __restrict__ ri,
        const float* __restrict__ rf) {
    __shared__ unsigned long long sc[SCAP];       // 16 KB
    __shared__ unsigned long long s2[TCAP];       // 4 KB trimmed
    __shared__ unsigned sh[1024];                 // 4 KB hist
    __shared__ int s_n, s_m;
    __shared__ unsigned s_binLo;

    int task = blockIdx.x, t = threadIdx.x;
    int need = (task < 2 * B) ? K1 : K2;
    int cnt = g_candCount[task];
    if (t == 0) { s_n = 0; s_m = 0; }
    for (int i = t; i < 1024; i += 512) sh[i] = 0;
    __syncthreads();

    const unsigned long long* rankSrc;
    int n2;
    if (cnt >= need && cnt <= SCAP) {
        // load candidates + fine histogram of (key>>16)-KEYB16
        for (int i = t; i < cnt; i += 512) {
            unsigned long long v = g_cand[task][i];
            sc[i] = v;
            unsigned bin = min((unsigned)(v >> 48) - KEYB16, 1023u);
            atomicAdd(&sh[bin], 1u);
        }
        __syncthreads();
        // bottom-up: smallest binLo with (cnt - prefix(binLo-1)) >= need
        if (t == 0) {
            unsigned pre = 0; unsigned binLo = 0;
            for (int i = 0; i < 1024; i++) {
                if (cnt - (int)(pre + sh[i]) < need) { binLo = i; break; }
                pre += sh[i];
            }
            s_binLo = binLo;
        }
        __syncthreads();
        unsigned binLo = s_binLo;
        // compact survivors (key bin >= binLo)
        for (int i = t; i < cnt; i += 512) {
            unsigned long long v = sc[i];
            unsigned bin = min((unsigned)(v >> 48) - KEYB16, 1023u);
            if (bin >= binLo) {
                int pos = atomicAdd(&s_m, 1);
                if (pos < TCAP) s2[pos] = v;
            }
        }
        __syncthreads();
        if (s_m <= TCAP) { rankSrc = s2; n2 = s_m; }
        else             { rankSrc = sc; n2 = cnt; }   // trim overflow: rank all
    } else {
        // exact fallback: radix-hist rescan of this task's row
        int a = task >> 5, row = task & 31;
        const float* src = (a == 0 ? rv : (a == 1 ? ri : rf)) + (size_t)row * NN;
        for (int i = t; i < NN; i += 512)
            atomicAdd(&sh[orderKey(src[i]) >> 22], 1u);
        __syncthreads();
        if (t == 0) {
            unsigned acc = 0; unsigned bi = 0;
            for (int i = 1023; i >= 0; i--) {
                acc += sh[i];
                if (acc >= (unsigned)need) { bi = i; break; }
            }
            s_binLo = bi << 22;
        }
        __syncthreads();
        unsigned binLo = s_binLo;
        for (int i = t; i < NN; i += 512) {
            unsigned k = orderKey(src[i]);
            if (k >= binLo) {
                int pos = atomicAdd(&s_n, 1);
                if (pos < SCAP)
                    sc[pos] = ((unsigned long long)k << 32) | (unsigned)(~(unsigned)i);
            }
        }
        __syncthreads();
        rankSrc = sc; n2 = min(s_n, SCAP);
    }

    // exact rank among survivors (composite: key desc, index asc)
    for (int i = t; i < n2; i += 512) {
        unsigned long long me = rankSrc[i];
        int r = 0;
        #pragma unroll 8
        for (int j = 0; j < n2; j++) r += (rankSrc[j] > me);
        if (r < need) g_topk[task][r] = (int)(~(unsigned)me);
    }
}

// ---------------------------------------------------------------------------
// 3) Coverage via dilated rf bitmap; last block finalizes + resets scratch
// ---------------------------------------------------------------------------
__global__ void __launch_bounds__(512) coverageKernel(float* __restrict__ out) {
    __shared__ unsigned bitmap[NN / 32];   // 32 KB: 512x512 bits
    __shared__ int s_rv[K1];
    __shared__ int s_cover, s_denom;
    __shared__ bool s_isLast;

    int b = blockIdx.x, t = threadIdx.x;
    for (int i = t; i < NN / 32; i += blockDim.x) bitmap[i] = 0;
    if (t == 0) { s_cover = 0; s_denom = 0; }
    for (int i = t; i < K1; i += blockDim.x) s_rv[i] = g_topk[0 * B + b][i];
    __syncthreads();

    // Dilate rf top-360 by Chebyshev radius 3
    if (t < K2) {
        int idx = g_topk[2 * B + b][t];
        int y = idx >> 9, x = idx & 511;
        int lo = max(x - 3, 0), hi = min(x + 3, 511);
        #pragma unroll
        for (int dy = -3; dy <= 3; dy++) {
            int yy = y + dy;
            if (yy < 0 || yy >= HH) continue;
            int wbase = yy << 4;
            int w0 = lo >> 5, w1 = hi >> 5;
            if (w0 == w1) {
                unsigned m = ((1u << (hi - lo + 1)) - 1u) << (lo & 31);
                atomicOr(&bitmap[wbase + w0], m);
            } else {
                atomicOr(&bitmap[wbase + w0], 0xFFFFFFFFu << (lo & 31));
                atomicOr(&bitmap[wbase + w1], (1u << ((hi & 31) + 1)) - 1u);
            }
        }
    }
    __syncthreads();

    // Probe union of rv and (ri \ rv)
    if (t < K2) {
        int idx; bool isSrc;
        if (t < K1) { idx = s_rv[t]; isSrc = true; }
        else {
            idx = g_topk[1 * B + b][t - K1];
            isSrc = true;
            for (int j = 0; j < K1; j++)
                if (s_rv[j] == idx) { isSrc = false; break; }
        }
        if (isSrc) {
            atomicAdd(&s_denom, 1);
            if ((bitmap[idx >> 5] >> (idx & 31)) & 1u) atomicAdd(&s_cover, 1);
        }
    }
    __syncthreads();
    if (t == 0) {
        g_loss[b] = 1.0f - (float)s_cover / (float)max(s_denom, 1);
        __threadfence();
        s_isLast = (atomicAdd(&g_done, 1) == B - 1);
    }
    __syncthreads();

    if (s_isLast) {
        if (t == 0) {
            volatile float* gl = g_loss;
            float s = 0.0f;
            for (int i = 0; i < B; i++) s += gl[i];
            out[0] = s / (float)B;
            g_done = 0;
        }
        if (t < NTASK) g_candCount[t] = 0;   // reset for next graph replay
    }
}

extern "C" void kernel_launch(void* const* d_in, const int* in_sizes, int n_in,
                              void* d_out, int out_size) {
    const float* rv = (const float*)d_in[0];
    const float* ri = (const float*)d_in[1];
    const float* rf = (const float*)d_in[2];

    collectKernel<<<NTASK * CH, 256>>>(rv, ri, rf);
    selectKernel<<<NTASK, 512>>>(rv, ri, rf);
    coverageKernel<<<B, 512>>>((float*)d_out);
}

// round 8
// speedup vs baseline: 1.4725x; 1.0045x over previous
#include <cuda_runtime.h>

#define B   32
#define HH  512
#define NN  (512*512)          // 262144 per row
#define K1  180
#define K2  360
#define NTASK 96               // 3 arrays x 32 rows
#define THRESH_F 2.75f
#define KEYB16  0xC030u        // orderKey(2.75f) >> 16
#define CAP  4096
#define SCAP 2048
#define TCAP 512               // trimmed candidate cap
#define CH   32                // chunks per task
#define CHUNKF (NN/CH)         // 8192 floats per block

// Scratch (static device globals: allocation-free, zeroed at load)
__device__ int                 g_candCount[NTASK];
__device__ unsigned long long  g_cand[NTASK][CAP];
__device__ int                 g_topk[NTASK][K2];
__device__ float               g_loss[B];
__device__ int                 g_done;

// Monotonic float -> uint (order-preserving), branchless
__device__ __forceinline__ unsigned orderKey(float f) {
    unsigned u = __float_as_uint(f);
    return u ^ (((unsigned)((int)u >> 31)) | 0x80000000u);
}

// Warp-aggregated emit of components >= THRESH_F
__device__ __forceinline__ void emit4(float4 v, unsigned gi0, int task) {
    float m = fmaxf(fmaxf(v.x, v.y), fmaxf(v.z, v.w));
    if (!__any_sync(0xffffffffu, m >= THRESH_F)) return;
    int lane = threadIdx.x & 31;
    float fx[4] = { v.x, v.y, v.z, v.w };
    #pragma unroll
    for (int c = 0; c < 4; c++) {
        bool pred = fx[c] >= THRESH_F;
        unsigned mask = __ballot_sync(0xffffffffu, pred);
        if (mask) {
            int leader = __ffs(mask) - 1;
            int base = 0;
            if (lane == leader)
                base = atomicAdd(&g_candCount[task], __popc(mask));
            base = __shfl_sync(0xffffffffu, base, leader);
            if (pred) {
                int pos = base + __popc(mask & ((1u << lane) - 1u));
                if (pos < CAP)
                    g_cand[task][pos] =
                        ((unsigned long long)orderKey(fx[c]) << 32) |
                        (unsigned)(~(gi0 + c));
            }
        }
    }
}

// ---------------------------------------------------------------------------
// 1) Streaming collect: 256 thr/block, 8 batched float4 loads (MLP=8)
// ---------------------------------------------------------------------------
__global__ void __launch_bounds__(256) collectKernel(
        const float* __restrict__ rv,
        const float* __restrict__ ri,
        const float* __restrict__ rf) {
    int task  = blockIdx.x >> 5;       // 0..95
    int chunk = blockIdx.x & 31;
    int a = task >> 5, row = task & 31;

    const float* src = (a == 0 ? rv : (a == 1 ? ri : rf))
                       + (size_t)row * NN + (size_t)chunk * CHUNKF;
    const float4* p = (const float4*)src;
    unsigned idxBase = (unsigned)chunk * CHUNKF;
    int t = threadIdx.x;

    float4 v[8];
    #pragma unroll
    for (int q = 0; q < 8; q++) v[q] = p[t + q * 256];   // front-batched: MLP=8
    #pragma unroll
    for (int q = 0; q < 8; q++)
        emit4(v[q], idxBase + (unsigned)(t + q * 256) * 4, task);
}

// ---------------------------------------------------------------------------
// 2) Exact top-k per task: fine-hist trim (~780 -> ~400), then rank trimmed.
// ---------------------------------------------------------------------------
__global__ void __launch_bounds__(512) selectKernel(
        const float* __restrict__ rv,
        const float* __restrict__ ri,
        const float* __restrict__ rf) {
    __shared__ unsigned long long sc[SCAP];       // 16 KB
    __shared__ unsigned long long s2[TCAP];       // 4 KB trimmed
    __shared__ unsigned sh[1024];                 // 4 KB hist
    __shared__ int s_n, s_m;
    __shared__ unsigned s_binLo;

    int task = blockIdx.x, t = threadIdx.x;
    int need = (task < 2 * B) ? K1 : K2;
    int cnt = g_candCount[task];
    if (t == 0) { s_n = 0; s_m = 0; }
    for (int i = t; i < 1024; i += 512) sh[i] = 0;
    __syncthreads();

    const unsigned long long* rankSrc;
    int n2;
    if (cnt >= need && cnt <= SCAP) {
        // load candidates + fine histogram of (key>>16)-KEYB16
        for (int i = t; i < cnt; i += 512) {
            unsigned long long v = g_cand[task][i];
            sc[i] = v;
            unsigned bin = min((unsigned)(v >> 48) - KEYB16, 1023u);
            atomicAdd(&sh[bin], 1u);
        }
        __syncthreads();
        // bottom-up: smallest binLo with (cnt - prefix(binLo-1)) >= need
        if (t == 0) {
            unsigned pre = 0; unsigned binLo = 0;
            for (int i = 0; i < 1024; i++) {
                if (cnt - (int)(pre + sh[i]) < need) { binLo = i; break; }
                pre += sh[i];
            }
            s_binLo = binLo;
        }
        __syncthreads();
        unsigned binLo = s_binLo;
        // compact survivors (key bin >= binLo)
        for (int i = t; i < cnt; i += 512) {
            unsigned long long v = sc[i];
            unsigned bin = min((unsigned)(v >> 48) - KEYB16, 1023u);
            if (bin >= binLo) {
                int pos = atomicAdd(&s_m, 1);
                if (pos < TCAP) s2[pos] = v;
            }
        }
        __syncthreads();
        if (s_m <= TCAP) { rankSrc = s2; n2 = s_m; }
        else             { rankSrc = sc; n2 = cnt; }   // trim overflow: rank all
    } else {
        // exact fallback: radix-hist rescan of this task's row
        int a = task >> 5, row = task & 31;
        const float* src = (a == 0 ? rv : (a == 1 ? ri : rf)) + (size_t)row * NN;
        for (int i = t; i < NN; i += 512)
            atomicAdd(&sh[orderKey(src[i]) >> 22], 1u);
        __syncthreads();
        if (t == 0) {
            unsigned acc = 0; unsigned bi = 0;
            for (int i = 1023; i >= 0; i--) {
                acc += sh[i];
                if (acc >= (unsigned)need) { bi = i; break; }
            }
            s_binLo = bi << 22;
        }
        __syncthreads();
        unsigned binLo = s_binLo;
        for (int i = t; i < NN; i += 512) {
            unsigned k = orderKey(src[i]);
            if (k >= binLo) {
                int pos = atomicAdd(&s_n, 1);
                if (pos < SCAP)
                    sc[pos] = ((unsigned long long)k << 32) | (unsigned)(~(unsigned)i);
            }
        }
        __syncthreads();
        rankSrc = sc; n2 = min(s_n, SCAP);
    }

    // exact rank among survivors (composite: key desc, index asc)
    for (int i = t; i < n2; i += 512) {
        unsigned long long me = rankSrc[i];
        int r = 0;
        #pragma unroll 8
        for (int j = 0; j < n2; j++) r += (rankSrc[j] > me);
        if (r < need) g_topk[task][r] = (int)(~(unsigned)me);
    }
}

// ---------------------------------------------------------------------------
// 3) Coverage via dilated rf bitmap; last block finalizes + resets scratch
// ---------------------------------------------------------------------------
__global__ void __launch_bounds__(512) coverageKernel(float* __restrict__ out) {
    __shared__ unsigned bitmap[NN / 32];   // 32 KB: 512x512 bits
    __shared__ int s_rv[K1];
    __shared__ int s_cover, s_denom;
    __shared__ bool s_isLast;

    int b = blockIdx.x, t = threadIdx.x;
    for (int i = t; i < NN / 32; i += blockDim.x) bitmap[i] = 0;
    if (t == 0) { s_cover = 0; s_denom = 0; }
    for (int i = t; i < K1; i += blockDim.x) s_rv[i] = g_topk[0 * B + b][i];
    __syncthreads();

    // Dilate rf top-360 by Chebyshev radius 3
    if (t < K2) {
        int idx = g_topk[2 * B + b][t];
        int y = idx >> 9, x = idx & 511;
        int lo = max(x - 3, 0), hi = min(x + 3, 511);
        #pragma unroll
        for (int dy = -3; dy <= 3; dy++) {
            int yy = y + dy;
            if (yy < 0 || yy >= HH) continue;
            int wbase = yy << 4;
            int w0 = lo >> 5, w1 = hi >> 5;
            if (w0 == w1) {
                unsigned m = ((1u << (hi - lo + 1)) - 1u) << (lo & 31);
                atomicOr(&bitmap[wbase + w0], m);
            } else {
                atomicOr(&bitmap[wbase + w0], 0xFFFFFFFFu << (lo & 31));
                atomicOr(&bitmap[wbase + w1], (1u << ((hi & 31) + 1)) - 1u);
            }
        }
    }
    __syncthreads();

    // Probe union of rv and (ri \ rv)
    if (t < K2) {
        int idx; bool isSrc;
        if (t < K1) { idx = s_rv[t]; isSrc = true; }
        else {
            idx = g_topk[1 * B + b][t - K1];
            isSrc = true;
            for (int j = 0; j < K1; j++)
                if (s_rv[j] == idx) { isSrc = false; break; }
        }
        if (isSrc) {
            atomicAdd(&s_denom, 1);
            if ((bitmap[idx >> 5] >> (idx & 31)) & 1u) atomicAdd(&s_cover, 1);
        }
    }
    __syncthreads();
    if (t == 0) {
        g_loss[b] = 1.0f - (float)s_cover / (float)max(s_denom, 1);
        __threadfence();
        s_isLast = (atomicAdd(&g_done, 1) == B - 1);
    }
    __syncthreads();

    if (s_isLast) {
        if (t == 0) {
            volatile float* gl = g_loss;
            float s = 0.0f;
            for (int i = 0; i < B; i++) s += gl[i];
            out[0] = s / (float)B;
            g_done = 0;
        }
        if (t < NTASK) g_candCount[t] = 0;   // reset for next graph replay
    }
}

extern "C" void kernel_launch(void* const* d_in, const int* in_sizes, int n_in,
                              void* d_out, int out_size) {
    const float* rv = (const float*)d_in[0];
    const float* ri = (const float*)d_in[1];
    const float* rf = (const float*)d_in[2];

    collectKernel<<<NTASK * CH, 256>>>(rv, ri, rf);
    selectKernel<<<NTASK, 512>>>(rv, ri, rf);
    coverageKernel<<<B, 512>>>((float*)d_out);
}

// round 9
// speedup vs baseline: 2.8290x; 1.9212x over previous
#include <cuda_runtime.h>

#define B   32
#define HH  512
#define NN  (512*512)          // 262144 per row
#define K1  180
#define K2  360
#define NTASK 96               // 3 arrays x 32 rows
#define THRESH_F 2.75f
#define KEYB16  0xC030u        // orderKey(2.75f) >> 16
#define CAP  4096
#define SCAP 2048
#define TCAP 512
#define CH   8                 // chunks per task
#define CHUNKF (NN/CH)         // 32768 floats per block

__device__ int                 g_candCount[NTASK];
__device__ unsigned long long  g_cand[NTASK][CAP];
__device__ int                 g_topk[NTASK][K2];
__device__ float               g_loss[B];
__device__ int                 g_done;

__device__ __forceinline__ unsigned orderKey(float f) {
    unsigned u = __float_as_uint(f);
    return u ^ (((unsigned)((int)u >> 31)) | 0x80000000u);
}

// ---------------------------------------------------------------------------
// 1) Collect. Pass A: vote-free streaming compare -> 64-bit hit mask.
//    Pass B: rare warp-aggregated emit (values reloaded; L1/L2 hits).
// ---------------------------------------------------------------------------
__global__ void __launch_bounds__(512) collectKernel(
        const float* __restrict__ rv,
        const float* __restrict__ ri,
        const float* __restrict__ rf) {
    int task  = blockIdx.x >> 3;       // 0..95
    int chunk = blockIdx.x & 7;
    int a = task >> 5, row = task & 31;

    const float* srcf = (a == 0 ? rv : (a == 1 ? ri : rf))
                        + (size_t)row * NN + (size_t)chunk * CHUNKF;
    const float4* p = (const float4*)srcf;
    unsigned idxBase = (unsigned)chunk * CHUNKF;
    int t = threadIdx.x;
    int lane = t & 31;

    // ---- Pass A: 16 float4 per thread, compare-only (no votes/branches) ----
    unsigned long long mask = 0ull;
    #pragma unroll
    for (int g = 0; g < 4; g++) {
        float4 w0 = p[t + (g * 4 + 0) * 512];
        float4 w1 = p[t + (g * 4 + 1) * 512];
        float4 w2 = p[t + (g * 4 + 2) * 512];
        float4 w3 = p[t + (g * 4 + 3) * 512];
        const float4 w[4] = { w0, w1, w2, w3 };
        #pragma unroll
        for (int u = 0; u < 4; u++) {
            unsigned bits = (unsigned)(w[u].x >= THRESH_F)
                          | ((unsigned)(w[u].y >= THRESH_F) << 1)
                          | ((unsigned)(w[u].z >= THRESH_F) << 2)
                          | ((unsigned)(w[u].w >= THRESH_F) << 3);
            mask |= (unsigned long long)bits << ((g * 4 + u) * 4);
        }
    }

    // ---- Pass B: drain masks with warp-aggregated appends ----
    unsigned long long m = mask;
    while (__any_sync(0xffffffffu, m != 0ull)) {
        bool pred = (m != 0ull);
        int bpos = pred ? (__ffsll(m) - 1) : 0;
        if (pred) m &= (m - 1ull);
        unsigned bal = __ballot_sync(0xffffffffu, pred);
        int leader = __ffs(bal) - 1;
        int base = 0;
        if (lane == leader)
            base = atomicAdd(&g_candCount[task], __popc(bal));
        base = __shfl_sync(0xffffffffu, base, leader);
        if (pred) {
            int slot = bpos >> 2, c = bpos & 3;
            int eoff = (t + slot * 512) * 4 + c;
            float f = srcf[eoff];                       // L1/L2 hit
            unsigned gi = idxBase + (unsigned)eoff;
            int pos = base + __popc(bal & ((1u << lane) - 1u));
            if (pos < CAP)
                g_cand[task][pos] =
                    ((unsigned long long)orderKey(f) << 32) | (unsigned)(~gi);
        }
    }
}

// ---------------------------------------------------------------------------
// 2) Exact top-k per task: fine-hist trim (~780 -> ~400), then rank trimmed.
// ---------------------------------------------------------------------------
__global__ void __launch_bounds__(512) selectKernel(
        const float* __restrict__ rv,
        const float* __restrict__ ri,
        const float* __restrict__ rf) {
    __shared__ unsigned long long sc[SCAP];
    __shared__ unsigned long long s2[TCAP];
    __shared__ unsigned sh[1024];
    __shared__ int s_n, s_m;
    __shared__ unsigned s_binLo;

    int task = blockIdx.x, t = threadIdx.x;
    int need = (task < 2 * B) ? K1 : K2;
    int cnt = g_candCount[task];
    if (t == 0) { s_n = 0; s_m = 0; }
    for (int i = t; i < 1024; i += 512) sh[i] = 0;
    __syncthreads();

    const unsigned long long* rankSrc;
    int n2;
    if (cnt >= need && cnt <= SCAP) {
        for (int i = t; i < cnt; i += 512) {
            unsigned long long v = g_cand[task][i];
            sc[i] = v;
            unsigned bin = min((unsigned)(v >> 48) - KEYB16, 1023u);
            atomicAdd(&sh[bin], 1u);
        }
        __syncthreads();
        if (t == 0) {
            unsigned pre = 0; unsigned binLo = 0;
            for (int i = 0; i < 1024; i++) {
                if (cnt - (int)(pre + sh[i]) < need) { binLo = i; break; }
                pre += sh[i];
            }
            s_binLo = binLo;
        }
        __syncthreads();
        unsigned binLo = s_binLo;
        for (int i = t; i < cnt; i += 512) {
            unsigned long long v = sc[i];
            unsigned bin = min((unsigned)(v >> 48) - KEYB16, 1023u);
            if (bin >= binLo) {
                int pos = atomicAdd(&s_m, 1);
                if (pos < TCAP) s2[pos] = v;
            }
        }
        __syncthreads();
        if (s_m <= TCAP) { rankSrc = s2; n2 = s_m; }
        else             { rankSrc = sc; n2 = cnt; }
    } else {
        // exact fallback: radix-hist rescan of this task's row
        int a = task >> 5, row = task & 31;
        const float* src = (a == 0 ? rv : (a == 1 ? ri : rf)) + (size_t)row * NN;
        for (int i = t; i < NN; i += 512)
            atomicAdd(&sh[orderKey(src[i]) >> 22], 1u);
        __syncthreads();
        if (t == 0) {
            unsigned acc = 0; unsigned bi = 0;
            for (int i = 1023; i >= 0; i--) {
                acc += sh[i];
                if (acc >= (unsigned)need) { bi = i; break; }
            }
            s_binLo = bi << 22;
        }
        __syncthreads();
        unsigned binLo = s_binLo;
        for (int i = t; i < NN; i += 512) {
            unsigned k = orderKey(src[i]);
            if (k >= binLo) {
                int pos = atomicAdd(&s_n, 1);
                if (pos < SCAP)
                    sc[pos] = ((unsigned long long)k << 32) | (unsigned)(~(unsigned)i);
            }
        }
        __syncthreads();
        rankSrc = sc; n2 = min(s_n, SCAP);
    }

    for (int i = t; i < n2; i += 512) {
        unsigned long long me = rankSrc[i];
        int r = 0;
        #pragma unroll 8
        for (int j = 0; j < n2; j++) r += (rankSrc[j] > me);
        if (r < need) g_topk[task][r] = (int)(~(unsigned)me);
    }
}

// ---------------------------------------------------------------------------
// 3) Coverage via dilated rf bitmap; last block finalizes + resets scratch
// ---------------------------------------------------------------------------
__global__ void __launch_bounds__(512) coverageKernel(float* __restrict__ out) {
    __shared__ unsigned bitmap[NN / 32];
    __shared__ int s_rv[K1];
    __shared__ int s_cover, s_denom;
    __shared__ bool s_isLast;

    int b = blockIdx.x, t = threadIdx.x;
    for (int i = t; i < NN / 32; i += blockDim.x) bitmap[i] = 0;
    if (t == 0) { s_cover = 0; s_denom = 0; }
    for (int i = t; i < K1; i += blockDim.x) s_rv[i] = g_topk[0 * B + b][i];
    __syncthreads();

    if (t < K2) {
        int idx = g_topk[2 * B + b][t];
        int y = idx >> 9, x = idx & 511;
        int lo = max(x - 3, 0), hi = min(x + 3, 511);
        #pragma unroll
        for (int dy = -3; dy <= 3; dy++) {
            int yy = y + dy;
            if (yy < 0 || yy >= HH) continue;
            int wbase = yy << 4;
            int w0 = lo >> 5, w1 = hi >> 5;
            if (w0 == w1) {
                unsigned msk = ((1u << (hi - lo + 1)) - 1u) << (lo & 31);
                atomicOr(&bitmap[wbase + w0], msk);
            } else {
                atomicOr(&bitmap[wbase + w0], 0xFFFFFFFFu << (lo & 31));
                atomicOr(&bitmap[wbase + w1], (1u << ((hi & 31) + 1)) - 1u);
            }
        }
    }
    __syncthreads();

    if (t < K2) {
        int idx; bool isSrc;
        if (t < K1) { idx = s_rv[t]; isSrc = true; }
        else {
            idx = g_topk[1 * B + b][t - K1];
            isSrc = true;
            for (int j = 0; j < K1; j++)
                if (s_rv[j] == idx) { isSrc = false; break; }
        }
        if (isSrc) {
            atomicAdd(&s_denom, 1);
            if ((bitmap[idx >> 5] >> (idx & 31)) & 1u) atomicAdd(&s_cover, 1);
        }
    }
    __syncthreads();
    if (t == 0) {
        g_loss[b] = 1.0f - (float)s_cover / (float)max(s_denom, 1);
        __threadfence();
        s_isLast = (atomicAdd(&g_done, 1) == B - 1);
    }
    __syncthreads();

    if (s_isLast) {
        if (t == 0) {
            volatile float* gl = g_loss;
            float s = 0.0f;
            for (int i = 0; i < B; i++) s += gl[i];
            out[0] = s / (float)B;
            g_done = 0;
        }
        if (t < NTASK) g_candCount[t] = 0;
    }
}

extern "C" void kernel_launch(void* const* d_in, const int* in_sizes, int n_in,
                              void* d_out, int out_size) {
    const float* rv = (const float*)d_in[0];
    const float* ri = (const float*)d_in[1];
    const float* rf = (const float*)d_in[2];

    collectKernel<<<NTASK * CH, 512>>>(rv, ri, rf);
    selectKernel<<<NTASK, 512>>>(rv, ri, rf);
    coverageKernel<<<B, 512>>>((float*)d_out);
}